// round 2
// baseline (speedup 1.0000x reference)
#include <cuda_runtime.h>
#include <math.h>

// Problem constants
#define B_   1024
#define T_   64
#define H_   512
#define V_   1024
#define GEN_ 100
#define H4_  2048

// Persistent state (device globals — no allocation allowed)
__device__ float d_hbuf[2][B_ * H_];   // ping-pong hidden state
__device__ float d_c[B_ * H_];         // cell state (read+write at same index only)
__device__ float d_bias[H4_];          // b_ih + b_hh
__device__ int   d_tok[B_];            // current token per batch row

__device__ __forceinline__ float sigm(float x) { return 1.0f / (1.0f + expf(-x)); }

// ---------------------------------------------------------------------------
// init: h0/c0 = input*W + b ; bias = b_ih + b_hh ; tok0 from onehots[:,0,:]
// grid: B_ blocks x 256 threads
// ---------------------------------------------------------------------------
__global__ void init_kernel(const float* __restrict__ input,
                            const float* __restrict__ onehots,
                            const float* __restrict__ Wh, const float* __restrict__ bh,
                            const float* __restrict__ Wc, const float* __restrict__ bc,
                            const float* __restrict__ b_ih, const float* __restrict__ b_hh)
{
    const int b = blockIdx.x;
    const int tid = threadIdx.x;
    const float xv = input[b];

    for (int i = tid; i < H_; i += 256) {
        d_hbuf[0][b * H_ + i] = xv * Wh[i] + bh[i];
        d_c[b * H_ + i]       = xv * Wc[i] + bc[i];
    }
    if (b < H4_ / 256) {
        const int j = b * 256 + tid;
        d_bias[j] = b_ih[j] + b_hh[j];
    }
    // one-hot: exactly one element > 0.5 in row (b, t=0)
    const float* oh = onehots + (size_t)b * T_ * V_;
    for (int v = tid; v < V_; v += 256)
        if (oh[v] > 0.5f) d_tok[b] = v;
}

// ---------------------------------------------------------------------------
// gates: g[b, q*512+h] = sum_k h[b,k]*W_hh[q*512+h, k]  (+ W_ih gather + bias)
// then fused LSTM cell. Tile: 64 b x 32 h x 4 gates, BK=16.
// grid: (16, 16) x 256 threads.  Reads d_hbuf[par], writes d_hbuf[par^1].
// ---------------------------------------------------------------------------
__global__ void gates_kernel(const float* __restrict__ Whh,
                             const float* __restrict__ Wih,
                             int par)
{
    __shared__ float hs[64][17];    // [b_local][k]  (pad 17: conflict-free)
    __shared__ float ws[128][17];   // [q*32 + h_local][k]

    const float* __restrict__ hin  = d_hbuf[par];
    float* __restrict__       hout = d_hbuf[par ^ 1];

    const int tx = threadIdx.x & 31;   // h within tile
    const int ty = threadIdx.x >> 5;   // b group
    const int b0 = blockIdx.x * 64;
    const int h0 = blockIdx.y * 32;

    float acc[8][4];
#pragma unroll
    for (int u = 0; u < 8; u++) {
        acc[u][0] = 0.f; acc[u][1] = 0.f; acc[u][2] = 0.f; acc[u][3] = 0.f;
    }

    for (int k0 = 0; k0 < H_; k0 += 16) {
#pragma unroll
        for (int i = threadIdx.x; i < 64 * 16; i += 256) {
            const int r = i >> 4, c = i & 15;
            hs[r][c] = hin[(b0 + r) * H_ + k0 + c];
        }
#pragma unroll
        for (int i = threadIdx.x; i < 128 * 16; i += 256) {
            const int r = i >> 4, c = i & 15;
            const int q = r >> 5, hh = r & 31;
            ws[r][c] = Whh[(q * H_ + h0 + hh) * H_ + k0 + c];
        }
        __syncthreads();

#pragma unroll
        for (int kk = 0; kk < 16; kk++) {
            const float wv0 = ws[tx][kk];
            const float wv1 = ws[32 + tx][kk];
            const float wv2 = ws[64 + tx][kk];
            const float wv3 = ws[96 + tx][kk];
#pragma unroll
            for (int u = 0; u < 8; u++) {
                const float hv = hs[ty + 8 * u][kk];
                acc[u][0] += hv * wv0;
                acc[u][1] += hv * wv1;
                acc[u][2] += hv * wv2;
                acc[u][3] += hv * wv3;
            }
        }
        __syncthreads();
    }

    const int hcol = h0 + tx;
#pragma unroll
    for (int u = 0; u < 8; u++) {
        const int b = b0 + ty + 8 * u;
        const int tok = d_tok[b];
        const float gi = acc[u][0] + Wih[(0 * H_ + hcol) * V_ + tok] + d_bias[0 * H_ + hcol];
        const float gf = acc[u][1] + Wih[(1 * H_ + hcol) * V_ + tok] + d_bias[1 * H_ + hcol];
        const float gg = acc[u][2] + Wih[(2 * H_ + hcol) * V_ + tok] + d_bias[2 * H_ + hcol];
        const float go = acc[u][3] + Wih[(3 * H_ + hcol) * V_ + tok] + d_bias[3 * H_ + hcol];

        const float cold = d_c[b * H_ + hcol];
        const float cnew = sigm(gf) * cold + sigm(gi) * tanhf(gg);
        const float hnew = sigm(go) * tanhf(cnew);
        d_c[b * H_ + hcol]  = cnew;
        hout[b * H_ + hcol] = hnew;
    }
}

// ---------------------------------------------------------------------------
// head: z1 = relu(h@W1.T + b1); z2 = z1@W2.T + b2; log_softmax; argmax -> tok
// One block handles 8 batch rows. grid: 128 x 256 threads.
// Reads d_hbuf[par] (the freshly-written state).
// ---------------------------------------------------------------------------
__global__ void head_kernel(const float* __restrict__ W1, const float* __restrict__ b1,
                            const float* __restrict__ W2, const float* __restrict__ b2,
                            float* __restrict__ out, int t, int par)
{
    __shared__ float sbuf[8 * 1024];   // phase 1: h tiles (8x512); phase 3: z2 (8x1024)
    __shared__ float z1s[8][104];      // padded rows: 416B, 16B-aligned for float4
    __shared__ float lse_s[8];

    const float* __restrict__ hbuf = d_hbuf[par];
    const int tid = threadIdx.x;
    const int b0 = blockIdx.x * 8;

    float (*hs)[512] = (float (*)[512])sbuf;
    for (int i = tid; i < 8 * 512; i += 256)
        hs[i >> 9][i & 511] = hbuf[(size_t)(b0 + (i >> 9)) * H_ + (i & 511)];
    __syncthreads();

    // z1: 800 dot products of length 512
    for (int idx = tid; idx < 8 * GEN_; idx += 256) {
        const int bi = idx / GEN_;
        const int g  = idx - bi * GEN_;
        const float4* wp = (const float4*)(W1 + (size_t)g * H_);
        const float4* hp = (const float4*)hs[bi];
        float s = 0.f;
        for (int k = 0; k < H_ / 4; k++) {
            const float4 w = wp[k], h = hp[k];
            s += w.x * h.x + w.y * h.y + w.z * h.z + w.w * h.w;
        }
        z1s[bi][g] = fmaxf(s + b1[g], 0.f);
    }
    __syncthreads();   // hs dead after this point; sbuf reused as z2

    float (*z2s)[1024] = (float (*)[1024])sbuf;
    for (int vc = 0; vc < 4; vc++) {
        const int v = vc * 256 + tid;
        float acc[8];
#pragma unroll
        for (int bi = 0; bi < 8; bi++) acc[bi] = 0.f;
        const float4* wp = (const float4*)(W2 + (size_t)v * GEN_);  // 400B rows: 16B aligned
#pragma unroll
        for (int k4 = 0; k4 < GEN_ / 4; k4++) {
            const float4 w = wp[k4];
#pragma unroll
            for (int bi = 0; bi < 8; bi++) {
                const float4 z = *(const float4*)&z1s[bi][k4 * 4];
                acc[bi] += w.x * z.x + w.y * z.y + w.z * z.z + w.w * z.w;
            }
        }
        const float bv = b2[v];
#pragma unroll
        for (int bi = 0; bi < 8; bi++) z2s[bi][v] = acc[bi] + bv;
    }
    __syncthreads();

    // per-warp reduction: warp w owns batch row b0+w
    const int w = tid >> 5, lane = tid & 31;
    {
        float m = -3.0e38f; int mi = 0;
        for (int v = lane; v < V_; v += 32) {
            const float x = z2s[w][v];
            if (x > m) { m = x; mi = v; }       // first occurrence kept (lowest index)
        }
#pragma unroll
        for (int off = 16; off; off >>= 1) {
            const float om  = __shfl_down_sync(0xffffffffu, m, off);
            const int   omi = __shfl_down_sync(0xffffffffu, mi, off);
            if (om > m || (om == m && omi < mi)) { m = om; mi = omi; }
        }
        m  = __shfl_sync(0xffffffffu, m, 0);
        mi = __shfl_sync(0xffffffffu, mi, 0);

        float s = 0.f;
        for (int v = lane; v < V_; v += 32) s += expf(z2s[w][v] - m);
#pragma unroll
        for (int off = 16; off; off >>= 1) s += __shfl_down_sync(0xffffffffu, s, off);

        if (lane == 0) {
            lse_s[w] = m + logf(s);
            d_tok[b0 + w] = mi;
        }
    }
    __syncthreads();

    float* orow = out + (size_t)t * B_ * V_ + (size_t)b0 * V_;
    for (int i = tid; i < 8 * 1024; i += 256)
        orow[i] = z2s[i >> 10][i & 1023] - lse_s[i >> 10];
}

// ---------------------------------------------------------------------------
// kernel_launch: init + 64 x (gates, head). 129 graph nodes, no syncs/allocs.
// Input order per metadata: input, onehots, digits, teacher, Wh, bh, Wc, bc,
//                           W_ih, W_hh, b_ih, b_hh, W1, b1, W2, b2
// ---------------------------------------------------------------------------
extern "C" void kernel_launch(void* const* d_in, const int* in_sizes, int n_in,
                              void* d_out, int out_size)
{
    const float* input   = (const float*)d_in[0];
    const float* onehots = (const float*)d_in[1];
    // d_in[2] = digits (unused), d_in[3] = teacher (always 0)
    const float* Wh   = (const float*)d_in[4];
    const float* bh   = (const float*)d_in[5];
    const float* Wc   = (const float*)d_in[6];
    const float* bc   = (const float*)d_in[7];
    const float* W_ih = (const float*)d_in[8];
    const float* W_hh = (const float*)d_in[9];
    const float* b_ih = (const float*)d_in[10];
    const float* b_hh = (const float*)d_in[11];
    const float* W1   = (const float*)d_in[12];
    const float* b1   = (const float*)d_in[13];
    const float* W2   = (const float*)d_in[14];
    const float* b2   = (const float*)d_in[15];
    float* out = (float*)d_out;

    init_kernel<<<B_, 256>>>(input, onehots, Wh, bh, Wc, bc, b_ih, b_hh);

    int par = 0;
    for (int t = 0; t < T_; t++) {
        dim3 g1(16, 16);
        gates_kernel<<<g1, 256>>>(W_hh, W_ih, par);
        head_kernel<<<128, 256>>>(W1, b1, W2, b2, out, t, par ^ 1);
        par ^= 1;
    }
}

// round 3
// speedup vs baseline: 1.9667x; 1.9667x over previous
#include <cuda_runtime.h>
#include <math.h>

// Problem constants
#define B_   1024
#define T_   64
#define H_   512
#define V_   1024
#define GEN_ 100
#define H4_  2048

// Persistent state (device globals — no allocation allowed)
__device__ float d_hbuf[2][B_ * H_];   // ping-pong hidden state
__device__ float d_c[B_ * H_];         // cell state
__device__ float d_bias[H4_];          // b_ih + b_hh
__device__ int   d_tok[B_];            // current token per batch row

__device__ __forceinline__ float sigm(float x) { return 1.0f / (1.0f + expf(-x)); }

// ---------------------------------------------------------------------------
// init: h0/c0 = input*W + b ; bias = b_ih + b_hh ; tok0 from onehots[:,0,:]
// ---------------------------------------------------------------------------
__global__ void init_kernel(const float* __restrict__ input,
                            const float* __restrict__ onehots,
                            const float* __restrict__ Wh, const float* __restrict__ bh,
                            const float* __restrict__ Wc, const float* __restrict__ bc,
                            const float* __restrict__ b_ih, const float* __restrict__ b_hh)
{
    const int b = blockIdx.x;
    const int tid = threadIdx.x;
    const float xv = input[b];

    for (int i = tid; i < H_; i += 256) {
        d_hbuf[0][b * H_ + i] = xv * Wh[i] + bh[i];
        d_c[b * H_ + i]       = xv * Wc[i] + bc[i];
    }
    if (b < H4_ / 256) {
        const int j = b * 256 + tid;
        d_bias[j] = b_ih[j] + b_hh[j];
    }
    const float* oh = onehots + (size_t)b * T_ * V_;
    for (int v = tid; v < V_; v += 256)
        if (oh[v] > 0.5f) d_tok[b] = v;
}

// ---------------------------------------------------------------------------
// gates: tile 128 batch x (4 gates x 32 h). grid (8,16)=128 blocks (1 wave).
// 256 threads, each computes an 8(b) x 8(4g x 2h) register tile.
// Register-prefetch double buffering over BK=16 chunks.
// ---------------------------------------------------------------------------
__global__ void __launch_bounds__(256)
gates_kernel(const float* __restrict__ Whh,
             const float* __restrict__ Wih,
             int par)
{
    __shared__ float hsm[16][132];   // [k][b_local], pad 132
    __shared__ float wsm[16][132];   // [k][q*32+hh]

    const float* __restrict__ hin  = d_hbuf[par];
    float* __restrict__       hout = d_hbuf[par ^ 1];

    const int tid = threadIdx.x;
    const int tx = tid & 15;           // 2-h-column group
    const int ty = tid >> 4;           // 8-b-row group
    const int b0 = blockIdx.x * 128;
    const int h0 = blockIdx.y * 32;

    // Loader jobs: 512 float4 jobs per tile; thread owns jobs tid and tid+256.
    // job idx -> r = idx>>2 (0..127), k-quad kq = idx&3 (cols kq*4..kq*4+3)
    const int r0 = tid >> 2,          kq0 = (tid & 3) * 4;
    const int r1 = (tid + 256) >> 2,  kq1 = ((tid + 256) & 3) * 4;

    const float* hb0 = hin + (size_t)(b0 + r0) * H_ + kq0;
    const float* hb1 = hin + (size_t)(b0 + r1) * H_ + kq1;
    const int wrow0 = (r0 >> 5) * H_ + h0 + (r0 & 31);
    const int wrow1 = (r1 >> 5) * H_ + h0 + (r1 & 31);
    const float* wb0 = Whh + (size_t)wrow0 * H_ + kq0;
    const float* wb1 = Whh + (size_t)wrow1 * H_ + kq1;

    float acc[8][8];
#pragma unroll
    for (int u = 0; u < 8; u++)
#pragma unroll
        for (int j = 0; j < 8; j++) acc[u][j] = 0.f;

    // prefetch chunk 0
    float4 ph0 = *(const float4*)(hb0);
    float4 ph1 = *(const float4*)(hb1);
    float4 pw0 = *(const float4*)(wb0);
    float4 pw1 = *(const float4*)(wb1);

    for (int k0 = 0; k0 < H_; k0 += 16) {
        // store prefetched chunk to smem (transposed)
        hsm[kq0 + 0][r0] = ph0.x; hsm[kq0 + 1][r0] = ph0.y;
        hsm[kq0 + 2][r0] = ph0.z; hsm[kq0 + 3][r0] = ph0.w;
        hsm[kq1 + 0][r1] = ph1.x; hsm[kq1 + 1][r1] = ph1.y;
        hsm[kq1 + 2][r1] = ph1.z; hsm[kq1 + 3][r1] = ph1.w;
        wsm[kq0 + 0][r0] = pw0.x; wsm[kq0 + 1][r0] = pw0.y;
        wsm[kq0 + 2][r0] = pw0.z; wsm[kq0 + 3][r0] = pw0.w;
        wsm[kq1 + 0][r1] = pw1.x; wsm[kq1 + 1][r1] = pw1.y;
        wsm[kq1 + 2][r1] = pw1.z; wsm[kq1 + 3][r1] = pw1.w;
        __syncthreads();

        if (k0 + 16 < H_) {                 // prefetch next chunk
            ph0 = *(const float4*)(hb0 + k0 + 16);
            ph1 = *(const float4*)(hb1 + k0 + 16);
            pw0 = *(const float4*)(wb0 + k0 + 16);
            pw1 = *(const float4*)(wb1 + k0 + 16);
        }

#pragma unroll
        for (int kk = 0; kk < 16; kk++) {
            const float4 a0 = *(const float4*)&hsm[kk][ty * 8];
            const float4 a1 = *(const float4*)&hsm[kk][ty * 8 + 4];
            const float2 w0 = *(const float2*)&wsm[kk][      tx * 2];
            const float2 w1 = *(const float2*)&wsm[kk][32  + tx * 2];
            const float2 w2 = *(const float2*)&wsm[kk][64  + tx * 2];
            const float2 w3 = *(const float2*)&wsm[kk][96  + tx * 2];
            const float hv[8] = {a0.x, a0.y, a0.z, a0.w, a1.x, a1.y, a1.z, a1.w};
#pragma unroll
            for (int u = 0; u < 8; u++) {
                acc[u][0] += hv[u] * w0.x; acc[u][1] += hv[u] * w0.y;
                acc[u][2] += hv[u] * w1.x; acc[u][3] += hv[u] * w1.y;
                acc[u][4] += hv[u] * w2.x; acc[u][5] += hv[u] * w2.y;
                acc[u][6] += hv[u] * w3.x; acc[u][7] += hv[u] * w3.y;
            }
        }
        __syncthreads();
    }

    // fused LSTM cell epilogue
    const int hbase = h0 + tx * 2;
    float bb[8];
#pragma unroll
    for (int q = 0; q < 4; q++) {
        bb[q * 2 + 0] = d_bias[q * H_ + hbase + 0];
        bb[q * 2 + 1] = d_bias[q * H_ + hbase + 1];
    }
#pragma unroll
    for (int u = 0; u < 8; u++) {
        const int b = b0 + ty * 8 + u;
        const int tok = d_tok[b];
        const float2 cold = *(const float2*)&d_c[b * H_ + hbase];
        float2 cnew, hnew;
#pragma unroll
        for (int jj = 0; jj < 2; jj++) {
            const int hcol = hbase + jj;
            const float gi = acc[u][0 + jj] + __ldg(&Wih[(size_t)(0 * H_ + hcol) * V_ + tok]) + bb[0 + jj];
            const float gf = acc[u][2 + jj] + __ldg(&Wih[(size_t)(1 * H_ + hcol) * V_ + tok]) + bb[2 + jj];
            const float gg = acc[u][4 + jj] + __ldg(&Wih[(size_t)(2 * H_ + hcol) * V_ + tok]) + bb[4 + jj];
            const float go = acc[u][6 + jj] + __ldg(&Wih[(size_t)(3 * H_ + hcol) * V_ + tok]) + bb[6 + jj];
            const float co = (jj == 0) ? cold.x : cold.y;
            const float cn = sigm(gf) * co + sigm(gi) * tanhf(gg);
            const float hn = sigm(go) * tanhf(cn);
            if (jj == 0) { cnew.x = cn; hnew.x = hn; }
            else         { cnew.y = cn; hnew.y = hn; }
        }
        *(float2*)&d_c[b * H_ + hbase]  = cnew;
        *(float2*)&hout[b * H_ + hbase] = hnew;
    }
}

// ---------------------------------------------------------------------------
// head: z1 = relu(h@W1.T+b1); z2 = z1@W2.T+b2; log-softmax; argmax -> tok
// 8 batch rows / block, 128 blocks x 256 threads.
// z1: warp-per-g with 8-row accumulators (W1 row read once per block).
// z2: v-per-thread with 8-row accumulators (independent FMA chains).
// ---------------------------------------------------------------------------
__global__ void __launch_bounds__(256)
head_kernel(const float* __restrict__ W1, const float* __restrict__ b1,
            const float* __restrict__ W2, const float* __restrict__ b2,
            float* __restrict__ out, int t, int par)
{
    __shared__ float sbuf[8 * 1024];   // phase 1: h (8x512); phase 2+: z2 (8x1024)
    __shared__ float z1s[8][104];      // row stride 416B (16B aligned)
    __shared__ float lse_s[8];

    const float* __restrict__ hbuf = d_hbuf[par];
    const int tid = threadIdx.x;
    const int b0 = blockIdx.x * 8;
    const int w = tid >> 5, lane = tid & 31;

    // load 8x512 h rows (coalesced float4)
    {
        float4* sb4 = (float4*)sbuf;
        const float4* hb4 = (const float4*)(hbuf + (size_t)b0 * H_);
        for (int i = tid; i < 8 * H_ / 4; i += 256) sb4[i] = hb4[i];
    }
    __syncthreads();

    // z1: warp per output column g, 8 batch accumulators
    for (int g = w; g < GEN_; g += 8) {
        float a[8];
#pragma unroll
        for (int bi = 0; bi < 8; bi++) a[bi] = 0.f;
        const float4* wp = (const float4*)(W1 + (size_t)g * H_);
#pragma unroll
        for (int p = 0; p < 4; p++) {
            const float4 wv = wp[p * 32 + lane];
#pragma unroll
            for (int bi = 0; bi < 8; bi++) {
                const float4 hv = *(const float4*)&sbuf[bi * H_ + (p * 32 + lane) * 4];
                a[bi] += wv.x * hv.x + wv.y * hv.y + wv.z * hv.z + wv.w * hv.w;
            }
        }
#pragma unroll
        for (int bi = 0; bi < 8; bi++) {
#pragma unroll
            for (int off = 16; off; off >>= 1)
                a[bi] += __shfl_down_sync(0xffffffffu, a[bi], off);
        }
        if (lane == 0) {
            const float bv = b1[g];
#pragma unroll
            for (int bi = 0; bi < 8; bi++)
                z1s[bi][g] = fmaxf(a[bi] + bv, 0.f);
        }
    }
    __syncthreads();   // h dead; sbuf becomes z2

    float (*z2s)[1024] = (float (*)[1024])sbuf;
#pragma unroll
    for (int vc = 0; vc < 4; vc++) {
        const int v = vc * 256 + tid;
        float acc[8];
#pragma unroll
        for (int bi = 0; bi < 8; bi++) acc[bi] = 0.f;
        const float4* wp = (const float4*)(W2 + (size_t)v * GEN_);
#pragma unroll
        for (int k4 = 0; k4 < GEN_ / 4; k4++) {
            const float4 wv = wp[k4];
#pragma unroll
            for (int bi = 0; bi < 8; bi++) {
                const float4 z = *(const float4*)&z1s[bi][k4 * 4];
                acc[bi] += wv.x * z.x + wv.y * z.y + wv.z * z.z + wv.w * z.w;
            }
        }
        const float bv = b2[v];
#pragma unroll
        for (int bi = 0; bi < 8; bi++) z2s[bi][v] = acc[bi] + bv;
    }
    __syncthreads();

    // per-warp reduction: warp w owns batch row b0+w
    {
        float m = -3.0e38f; int mi = 0;
        for (int v = lane; v < V_; v += 32) {
            const float x = z2s[w][v];
            if (x > m) { m = x; mi = v; }
        }
#pragma unroll
        for (int off = 16; off; off >>= 1) {
            const float om  = __shfl_down_sync(0xffffffffu, m, off);
            const int   omi = __shfl_down_sync(0xffffffffu, mi, off);
            if (om > m || (om == m && omi < mi)) { m = om; mi = omi; }
        }
        m  = __shfl_sync(0xffffffffu, m, 0);
        mi = __shfl_sync(0xffffffffu, mi, 0);

        float s = 0.f;
        for (int v = lane; v < V_; v += 32) s += expf(z2s[w][v] - m);
#pragma unroll
        for (int off = 16; off; off >>= 1) s += __shfl_down_sync(0xffffffffu, s, off);

        if (lane == 0) {
            lse_s[w] = m + logf(s);
            d_tok[b0 + w] = mi;
        }
    }
    __syncthreads();

    float* orow = out + (size_t)t * B_ * V_ + (size_t)b0 * V_;
    for (int i = tid; i < 8 * V_ / 4; i += 256) {
        const int bi = i >> 8;                    // 256 float4 per row
        float4 v4 = *(const float4*)&z2s[bi][(i & 255) * 4];
        const float l = lse_s[bi];
        v4.x -= l; v4.y -= l; v4.z -= l; v4.w -= l;
        *(float4*)&orow[i * 4] = v4;
    }
}

// ---------------------------------------------------------------------------
// kernel_launch: init + 64 x (gates, head)
// ---------------------------------------------------------------------------
extern "C" void kernel_launch(void* const* d_in, const int* in_sizes, int n_in,
                              void* d_out, int out_size)
{
    const float* input   = (const float*)d_in[0];
    const float* onehots = (const float*)d_in[1];
    const float* Wh   = (const float*)d_in[4];
    const float* bh   = (const float*)d_in[5];
    const float* Wc   = (const float*)d_in[6];
    const float* bc   = (const float*)d_in[7];
    const float* W_ih = (const float*)d_in[8];
    const float* W_hh = (const float*)d_in[9];
    const float* b_ih = (const float*)d_in[10];
    const float* b_hh = (const float*)d_in[11];
    const float* W1   = (const float*)d_in[12];
    const float* b1   = (const float*)d_in[13];
    const float* W2   = (const float*)d_in[14];
    const float* b2   = (const float*)d_in[15];
    float* out = (float*)d_out;

    init_kernel<<<B_, 256>>>(input, onehots, Wh, bh, Wc, bc, b_ih, b_hh);

    int par = 0;
    for (int t = 0; t < T_; t++) {
        dim3 g1(8, 16);
        gates_kernel<<<g1, 256>>>(W_hh, W_ih, par);
        head_kernel<<<128, 256>>>(W1, b1, W2, b2, out, t, par ^ 1);
        par ^= 1;
    }
}